// round 11
// baseline (speedup 1.0000x reference)
#include <cuda_runtime.h>
#include <cuda_fp16.h>
#include <cuda_bf16.h>

#define BATCH   512
#define CIN     2048
#define OFEAT   64
#define KDIM    16
#define MCOLS   1024
#define OUTW    2112

// Scratch (device globals; no allocs)
__device__ __nv_bfloat16 g_xh[BATCH * CIN];     // 2 MB
__device__ __nv_bfloat16 g_Th[CIN * MCOLS];     // 4 MB, [k][n]
__device__ __half        g_mh[BATCH * MCOLS];   // 1 MB

// ---------------------------------------------------------------------------
// Prep: convert x,T -> bf16, zero out[:, 2048:]. Uniform regions by blockIdx,
// 2 float4 per thread. blocks [0,512): x; [512,1536): T; [1536,1552): zero.
// ---------------------------------------------------------------------------
__global__ __launch_bounds__(256) void prep_kernel(
    const float* __restrict__ x, const float* __restrict__ T, float* __restrict__ out)
{
    const int bid = blockIdx.x;
    const int tid = threadIdx.x;
    if (bid < 512) {                             // x: 512*512 float4, 2/thread
        int base = bid * 512 + tid;
#pragma unroll
        for (int it = 0; it < 2; ++it) {
            int id = base + it * 256;
            float4 v = ((const float4*)x)[id];
            __nv_bfloat162* dst = (__nv_bfloat162*)&g_xh[id * 4];
            dst[0] = __floats2bfloat162_rn(v.x, v.y);
            dst[1] = __floats2bfloat162_rn(v.z, v.w);
        }
    } else if (bid < 1536) {                     // T: 2048*256 float4, 2/thread
        int base = (bid - 512) * 512 + tid;
#pragma unroll
        for (int it = 0; it < 2; ++it) {
            int i = base + it * 256;
            float4 v = ((const float4*)T)[i];
            __nv_bfloat162* dst = (__nv_bfloat162*)&g_Th[i * 4];
            dst[0] = __floats2bfloat162_rn(v.x, v.y);
            dst[1] = __floats2bfloat162_rn(v.z, v.w);
        }
    } else {                                     // zero tail: 8192 float4, 2/thread
        int base = (bid - 1536) * 512 + tid;
#pragma unroll
        for (int it = 0; it < 2; ++it) {
            int i = base + it * 256;
            int row = i >> 4, c = i & 15;
            ((float4*)&out[row * OUTW + CIN])[c] = make_float4(0.f, 0.f, 0.f, 0.f);
        }
    }
}

// ---------------------------------------------------------------------------
// GEMM bf16: m = x @ T, mma.m16n8k16, 4-stage cp.async ring.
// BM=64 BN=32 BK=32, 64 threads (2 warps, warp tile 32m x 32n).
// grid 32x8 = 256 blocks; tiny CTAs -> ~6 resident/SM hides stage latency;
// warp tile 32x32 -> 0.125 B LDS per MAC (4 LDSM : 8 MMA per k16).
// ---------------------------------------------------------------------------
__device__ __forceinline__ void cp16(unsigned s, const void* g) {
    asm volatile("cp.async.cg.shared.global [%0], [%1], 16;" :: "r"(s), "l"(g));
}
#define CP_COMMIT()  asm volatile("cp.async.commit_group;")
#define CP_WAIT(N)   asm volatile("cp.async.wait_group %0;" :: "n"(N))

__device__ __forceinline__ void ldm_x4(unsigned* r, unsigned addr) {
    asm volatile("ldmatrix.sync.aligned.m8n8.x4.shared.b16 {%0,%1,%2,%3}, [%4];"
        : "=r"(r[0]), "=r"(r[1]), "=r"(r[2]), "=r"(r[3]) : "r"(addr));
}
__device__ __forceinline__ void ldm_x4t(unsigned* r, unsigned addr) {
    asm volatile("ldmatrix.sync.aligned.m8n8.x4.trans.shared.b16 {%0,%1,%2,%3}, [%4];"
        : "=r"(r[0]), "=r"(r[1]), "=r"(r[2]), "=r"(r[3]) : "r"(addr));
}
__device__ __forceinline__ void mma_bf16(float* d, const unsigned* a, const unsigned* b) {
    asm volatile(
        "mma.sync.aligned.m16n8k16.row.col.f32.bf16.bf16.f32 "
        "{%0,%1,%2,%3}, {%4,%5,%6,%7}, {%8,%9}, {%0,%1,%2,%3};\n"
        : "+f"(d[0]), "+f"(d[1]), "+f"(d[2]), "+f"(d[3])
        : "r"(a[0]), "r"(a[1]), "r"(a[2]), "r"(a[3]), "r"(b[0]), "r"(b[1]));
}

#define NSTAGE 4
#define NPANEL 64   // CIN / 32

__global__ __launch_bounds__(64) void gemm_bf16(__half* __restrict__ mh)
{
    __shared__ __nv_bfloat16 As[NSTAGE][64][40];   // 80B row stride
    __shared__ __nv_bfloat16 Bs[NSTAGE][32][40];   // 80B row stride (32 cols used)

    const int tid  = threadIdx.x;
    const int lane = tid & 31;
    const int wid  = tid >> 5;     // 2 m-warps of 32
    const int row0 = blockIdx.y * 64;
    const int col0 = blockIdx.x * 32;

    // staging: A 64x32 (256 segs, 4/thread), B 32x32 (128 segs, 2/thread)
    const int aRow = tid;                       // one row per thread, 4 segs
    const int bRow = tid >> 1, bC = (tid & 1) * 16;

    const __nv_bfloat16* gA = &g_xh[(row0 + aRow) * CIN];
    const __nv_bfloat16* gB = &g_Th[bRow * MCOLS + col0 + bC];

    float d[2][4][4];
#pragma unroll
    for (int i = 0; i < 2; ++i)
#pragma unroll
        for (int j = 0; j < 4; ++j)
#pragma unroll
            for (int k = 0; k < 4; ++k) d[i][j][k] = 0.0f;

    // prologue: stages 0..2
#pragma unroll
    for (int s = 0; s < NSTAGE - 1; ++s) {
        const int k0 = s * 32;
#pragma unroll
        for (int c16 = 0; c16 < 4; ++c16)
            cp16(__cvta_generic_to_shared(&As[s][aRow][c16 * 8]), gA + k0 + c16 * 8);
        cp16(__cvta_generic_to_shared(&Bs[s][bRow][bC]),     &gB[k0 * MCOLS]);
        cp16(__cvta_generic_to_shared(&Bs[s][bRow][bC + 8]), &gB[k0 * MCOLS + 8]);
        CP_COMMIT();
    }

    for (int p = 0; p < NPANEL; ++p) {
        CP_WAIT(NSTAGE - 2);     // my stage-p copies complete
        __syncthreads();         // all copies visible; all threads done with p-1
        if (p + NSTAGE - 1 < NPANEL) {
            const int s  = (p + NSTAGE - 1) & (NSTAGE - 1);
            const int k0 = (p + NSTAGE - 1) * 32;
#pragma unroll
            for (int c16 = 0; c16 < 4; ++c16)
                cp16(__cvta_generic_to_shared(&As[s][aRow][c16 * 8]), gA + k0 + c16 * 8);
            cp16(__cvta_generic_to_shared(&Bs[s][bRow][bC]),     &gB[k0 * MCOLS]);
            cp16(__cvta_generic_to_shared(&Bs[s][bRow][bC + 8]), &gB[k0 * MCOLS + 8]);
        }
        CP_COMMIT();
        const int buf = p & (NSTAGE - 1);

#pragma unroll
        for (int kk = 0; kk < 32; kk += 16) {
            unsigned a[2][4], b[2][4];
#pragma unroll
            for (int ai = 0; ai < 2; ++ai) {
                unsigned adrA = __cvta_generic_to_shared(
                    &As[buf][wid * 32 + ai * 16 + (lane & 15)][kk + (lane >> 4) * 8]);
                ldm_x4(a[ai], adrA);
            }
#pragma unroll
            for (int bg = 0; bg < 2; ++bg) {
                unsigned adrB = __cvta_generic_to_shared(
                    &Bs[buf][kk + (lane & 15)][bg * 16 + (lane >> 4) * 8]);
                ldm_x4t(b[bg], adrB);
            }
#pragma unroll
            for (int ai = 0; ai < 2; ++ai)
#pragma unroll
                for (int bg = 0; bg < 2; ++bg) {
                    mma_bf16(d[ai][bg * 2],     a[ai], b[bg]);
                    mma_bf16(d[ai][bg * 2 + 1], a[ai], b[bg] + 2);
                }
        }
    }

    // epilogue -> fp16
    const int g = lane >> 2, c = lane & 3;
#pragma unroll
    for (int ai = 0; ai < 2; ++ai)
#pragma unroll
        for (int bi = 0; bi < 4; ++bi) {
            int row = row0 + wid * 32 + ai * 16 + g;
            int col = col0 + bi * 8 + c * 2;
            *(__half2*)&mh[row * MCOLS + col] =
                __floats2half2_rn(d[ai][bi][0], d[ai][bi][1]);
            *(__half2*)&mh[(row + 8) * MCOLS + col] =
                __floats2half2_rn(d[ai][bi][2], d[ai][bi][3]);
        }
}

// ---------------------------------------------------------------------------
// Pairwise: out[b, 2048+o] += sum_{j in chunk} exp(-L1(m[b,o,:], m[j,o,:]))
// grid (jc=8, bt=4, o=64) x 128 thr. Folds x -> out copy (one float4/thread).
// ---------------------------------------------------------------------------
__global__ __launch_bounds__(128) void pairwise_kernel(
    const __half* __restrict__ mh, const float* __restrict__ x, float* __restrict__ out)
{
    __shared__ uint4  sjt[64][2];
    __shared__ __half sgT[4][64];

    const int jc  = blockIdx.x;
    const int bt  = blockIdx.y;
    const int o   = blockIdx.z;
    const int tid = threadIdx.x;
    const int b   = bt * 128 + tid;

    {
        int id  = ((o * 4 + bt) * 8 + jc) * 128 + tid;
        int row = id >> 9, c4 = id & 511;
        ((float4*)&out[row * OUTW])[c4] = ((const float4*)&x[row * CIN])[c4];
    }

    const uint4* vp = (const uint4*)&mh[b * MCOLS + o * KDIM];
    uint4 u0 = vp[0], u1 = vp[1];
    __half2 v[8];
    *(uint4*)&v[0] = u0;
    *(uint4*)&v[4] = u1;
    __half2 vgb[4];
    {
        __half2 t01 = __hadd2(v[0], v[1]);
        __half2 t23 = __hadd2(v[2], v[3]);
        __half2 t45 = __hadd2(v[4], v[5]);
        __half2 t67 = __hadd2(v[6], v[7]);
        vgb[0] = __half2half2(__hadd(__low2half(t01), __high2half(t01)));
        vgb[1] = __half2half2(__hadd(__low2half(t23), __high2half(t23)));
        vgb[2] = __half2half2(__hadd(__low2half(t45), __high2half(t45)));
        vgb[3] = __half2half2(__hadd(__low2half(t67), __high2half(t67)));
    }

    if (tid < 64) {
        int j = jc * 64 + tid;
        const uint4* jp = (const uint4*)&mh[j * MCOLS + o * KDIM];
        uint4 w0 = jp[0], w1 = jp[1];
        sjt[tid][0] = w0;
        sjt[tid][1] = w1;
        __half2 s[8];
        *(uint4*)&s[0] = w0;
        *(uint4*)&s[4] = w1;
        __half2 a01 = __hadd2(s[0], s[1]);
        __half2 a23 = __hadd2(s[2], s[3]);
        __half2 a45 = __hadd2(s[4], s[5]);
        __half2 a67 = __hadd2(s[6], s[7]);
        sgT[0][tid] = __hadd(__low2half(a01), __high2half(a01));
        sgT[1][tid] = __hadd(__low2half(a23), __high2half(a23));
        sgT[2][tid] = __hadd(__low2half(a45), __high2half(a45));
        sgT[3][tid] = __hadd(__low2half(a67), __high2half(a67));
    }
    __syncthreads();

    float acc = 0.0f;
#pragma unroll 4
    for (int jp2 = 0; jp2 < 32; ++jp2) {
        __half2 e0 = __habs2(__hsub2(vgb[0], *(const __half2*)&sgT[0][jp2 * 2]));
        __half2 e1 = __habs2(__hsub2(vgb[1], *(const __half2*)&sgT[1][jp2 * 2]));
        __half2 e2 = __habs2(__hsub2(vgb[2], *(const __half2*)&sgT[2][jp2 * 2]));
        __half2 e3 = __habs2(__hsub2(vgb[3], *(const __half2*)&sgT[3][jp2 * 2]));
        __half2 et = __hadd2(__hadd2(e0, e1), __hadd2(e2, e3));
        float mn = __half2float(__hmin(__low2half(et), __high2half(et)));
        if (__any_sync(0xffffffffu, mn < 30.0f)) {
#pragma unroll
            for (int t = 0; t < 2; ++t) {
                const int jj = jp2 * 2 + t;
                __half2 s[8];
                *(uint4*)&s[0] = sjt[jj][0];
                *(uint4*)&s[4] = sjt[jj][1];
                __half2 q0 = __habs2(__hsub2(v[0], s[0]));
                __half2 q1 = __habs2(__hsub2(v[1], s[1]));
                __half2 q2 = __habs2(__hsub2(v[2], s[2]));
                __half2 q3 = __habs2(__hsub2(v[3], s[3]));
                __half2 q4 = __habs2(__hsub2(v[4], s[4]));
                __half2 q5 = __habs2(__hsub2(v[5], s[5]));
                __half2 q6 = __habs2(__hsub2(v[6], s[6]));
                __half2 q7 = __habs2(__hsub2(v[7], s[7]));
                __half2 sm = __hadd2(__hadd2(__hadd2(q0, q1), __hadd2(q2, q3)),
                                     __hadd2(__hadd2(q4, q5), __hadd2(q6, q7)));
                float dist = __low2float(sm) + __high2float(sm);
                acc += __expf(-dist);
            }
        }
    }

    atomicAdd(&out[b * OUTW + CIN + o], acc);
}

extern "C" void kernel_launch(void* const* d_in, const int* in_sizes, int n_in,
                              void* d_out, int out_size)
{
    const float* x = (const float*)d_in[0];
    const float* T = (const float*)d_in[1];
    float* out = (float*)d_out;

    __half* mh;
    cudaGetSymbolAddress((void**)&mh, g_mh);

    prep_kernel<<<1552, 256>>>(x, T, out);
    gemm_bf16<<<dim3(MCOLS / 32, BATCH / 64), 64>>>(mh);
    pairwise_kernel<<<dim3(8, 4, OFEAT), 128>>>(mh, x, out);
}

// round 12
// speedup vs baseline: 1.1565x; 1.1565x over previous
#include <cuda_runtime.h>
#include <cuda_fp16.h>
#include <cuda_bf16.h>

#define BATCH   512
#define CIN     2048
#define OFEAT   64
#define KDIM    16
#define MCOLS   1024
#define OUTW    2112
#define MSIZE   (BATCH * MCOLS)

// Scratch (device globals; no allocs)
__device__ __nv_bfloat16 g_xh[BATCH * CIN];     // 2 MB
__device__ __nv_bfloat16 g_Th[CIN * MCOLS];     // 4 MB, [k][n]
__device__ __half        g_mh[2 * MSIZE];       // 2 MB: split-K partials

// ---------------------------------------------------------------------------
// Prep: convert x,T -> bf16, zero out[:, 2048:]. Uniform regions by blockIdx,
// 2 float4 per thread. blocks [0,512): x; [512,1536): T; [1536,1552): zero.
// ---------------------------------------------------------------------------
__global__ __launch_bounds__(256) void prep_kernel(
    const float* __restrict__ x, const float* __restrict__ T, float* __restrict__ out)
{
    const int bid = blockIdx.x;
    const int tid = threadIdx.x;
    if (bid < 512) {                             // x: 512*512 float4, 2/thread
        int base = bid * 512 + tid;
#pragma unroll
        for (int it = 0; it < 2; ++it) {
            int id = base + it * 256;
            float4 v = ((const float4*)x)[id];
            __nv_bfloat162* dst = (__nv_bfloat162*)&g_xh[id * 4];
            dst[0] = __floats2bfloat162_rn(v.x, v.y);
            dst[1] = __floats2bfloat162_rn(v.z, v.w);
        }
    } else if (bid < 1536) {                     // T: 2048*256 float4, 2/thread
        int base = (bid - 512) * 512 + tid;
#pragma unroll
        for (int it = 0; it < 2; ++it) {
            int i = base + it * 256;
            float4 v = ((const float4*)T)[i];
            __nv_bfloat162* dst = (__nv_bfloat162*)&g_Th[i * 4];
            dst[0] = __floats2bfloat162_rn(v.x, v.y);
            dst[1] = __floats2bfloat162_rn(v.z, v.w);
        }
    } else {                                     // zero tail: 8192 float4, 2/thread
        int base = (bid - 1536) * 512 + tid;
#pragma unroll
        for (int it = 0; it < 2; ++it) {
            int i = base + it * 256;
            int row = i >> 4, c = i & 15;
            ((float4*)&out[row * OUTW + CIN])[c] = make_float4(0.f, 0.f, 0.f, 0.f);
        }
    }
}

// ---------------------------------------------------------------------------
// GEMM bf16 split-K: partial[z][512,1024] over K half z. mma.m16n8k16,
// 4-stage cp.async ring. BM=32 BN=64 BK=32, 128 threads (4 warps, 2m x 2n,
// warp tile 16x32). grid 16x16x2 = 512 blocks, 32 panels per block.
// ---------------------------------------------------------------------------
__device__ __forceinline__ void cp16(unsigned s, const void* g) {
    asm volatile("cp.async.cg.shared.global [%0], [%1], 16;" :: "r"(s), "l"(g));
}
#define CP_COMMIT()  asm volatile("cp.async.commit_group;")
#define CP_WAIT(N)   asm volatile("cp.async.wait_group %0;" :: "n"(N))

__device__ __forceinline__ void ldm_x4(unsigned* r, unsigned addr) {
    asm volatile("ldmatrix.sync.aligned.m8n8.x4.shared.b16 {%0,%1,%2,%3}, [%4];"
        : "=r"(r[0]), "=r"(r[1]), "=r"(r[2]), "=r"(r[3]) : "r"(addr));
}
__device__ __forceinline__ void ldm_x4t(unsigned* r, unsigned addr) {
    asm volatile("ldmatrix.sync.aligned.m8n8.x4.trans.shared.b16 {%0,%1,%2,%3}, [%4];"
        : "=r"(r[0]), "=r"(r[1]), "=r"(r[2]), "=r"(r[3]) : "r"(addr));
}
__device__ __forceinline__ void mma_bf16(float* d, const unsigned* a, const unsigned* b) {
    asm volatile(
        "mma.sync.aligned.m16n8k16.row.col.f32.bf16.bf16.f32 "
        "{%0,%1,%2,%3}, {%4,%5,%6,%7}, {%8,%9}, {%0,%1,%2,%3};\n"
        : "+f"(d[0]), "+f"(d[1]), "+f"(d[2]), "+f"(d[3])
        : "r"(a[0]), "r"(a[1]), "r"(a[2]), "r"(a[3]), "r"(b[0]), "r"(b[1]));
}

#define NSTAGE 4
#define NPANEL 32   // (CIN/2) / 32 per split

__global__ __launch_bounds__(128) void gemm_bf16(__half* __restrict__ mh)
{
    __shared__ __nv_bfloat16 As[NSTAGE][32][40];   // 80B row stride
    __shared__ __nv_bfloat16 Bs[NSTAGE][32][72];   // 144B row stride

    const int tid  = threadIdx.x;
    const int lane = tid & 31;
    const int wid  = tid >> 5;
    const int wm   = wid & 1;      // 2 m-warps of 16
    const int wn   = wid >> 1;     // 2 n-warps of 32
    const int row0 = blockIdx.y * 32;
    const int col0 = blockIdx.x * 64;
    const int kz   = blockIdx.z * (CIN / 2);

    // staging: A 32x32 (1 cp16/thread), B 32x64 (2 cp16/thread)
    const int aRow = tid >> 2, aC = (tid & 3) * 8;
    const int bRow = tid >> 2, bC = (tid & 3) * 16;

    const __nv_bfloat16* gA = &g_xh[(row0 + aRow) * CIN + kz + aC];
    const __nv_bfloat16* gB = &g_Th[(kz + bRow) * MCOLS + col0 + bC];

    float d[2][2][4];
#pragma unroll
    for (int i = 0; i < 2; ++i)
#pragma unroll
        for (int j = 0; j < 2; ++j)
#pragma unroll
            for (int k = 0; k < 4; ++k) d[i][j][k] = 0.0f;

    // prologue: stages 0..2
#pragma unroll
    for (int s = 0; s < NSTAGE - 1; ++s) {
        cp16(__cvta_generic_to_shared(&As[s][aRow][aC]), gA + s * 32);
        cp16(__cvta_generic_to_shared(&Bs[s][bRow][bC]),     gB + s * 32 * MCOLS);
        cp16(__cvta_generic_to_shared(&Bs[s][bRow][bC + 8]), gB + s * 32 * MCOLS + 8);
        CP_COMMIT();
    }

    for (int p = 0; p < NPANEL; ++p) {
        CP_WAIT(NSTAGE - 2);     // my stage-p copies complete
        __syncthreads();         // all copies visible; all threads done with p-1
        if (p + NSTAGE - 1 < NPANEL) {
            const int s  = (p + NSTAGE - 1) & (NSTAGE - 1);
            const int k0 = (p + NSTAGE - 1) * 32;
            cp16(__cvta_generic_to_shared(&As[s][aRow][aC]), gA + k0);
            cp16(__cvta_generic_to_shared(&Bs[s][bRow][bC]),     gB + k0 * MCOLS);
            cp16(__cvta_generic_to_shared(&Bs[s][bRow][bC + 8]), gB + k0 * MCOLS + 8);
        }
        CP_COMMIT();
        const int buf = p & (NSTAGE - 1);

#pragma unroll
        for (int kk = 0; kk < 32; kk += 16) {
            unsigned a[4];
            unsigned adrA = __cvta_generic_to_shared(
                &As[buf][wm * 16 + (lane & 15)][kk + (lane >> 4) * 8]);
            ldm_x4(a, adrA);
#pragma unroll
            for (int bi = 0; bi < 2; ++bi) {
                unsigned bb[4];
                unsigned adrB = __cvta_generic_to_shared(
                    &Bs[buf][kk + (lane & 15)][wn * 32 + bi * 16 + (lane >> 4) * 8]);
                ldm_x4t(bb, adrB);
                mma_bf16(d[bi][0], a, bb);
                mma_bf16(d[bi][1], a, bb + 2);
            }
        }
    }

    // epilogue -> fp16 partial buffer for this split
    __half* mo = mh + blockIdx.z * MSIZE;
    const int g = lane >> 2, c = lane & 3;
#pragma unroll
    for (int bi = 0; bi < 2; ++bi)
#pragma unroll
        for (int h = 0; h < 2; ++h) {
            int row = row0 + wm * 16 + g;
            int col = col0 + wn * 32 + bi * 16 + h * 8 + c * 2;
            *(__half2*)&mo[row * MCOLS + col] =
                __floats2half2_rn(d[bi][h][0], d[bi][h][1]);
            *(__half2*)&mo[(row + 8) * MCOLS + col] =
                __floats2half2_rn(d[bi][h][2], d[bi][h][3]);
        }
}

// ---------------------------------------------------------------------------
// Pairwise: combines the two split-K partials on load (hadd2), then
// out[b, 2048+o] += sum_{j in chunk} exp(-L1(m[b,o,:], m[j,o,:])).
// grid (jc=8, bt=4, o=64) x 128 thr. Folds x -> out copy (one float4/thread).
// ---------------------------------------------------------------------------
__global__ __launch_bounds__(128) void pairwise_kernel(
    const __half* __restrict__ mh, const float* __restrict__ x, float* __restrict__ out)
{
    __shared__ uint4  sjt[64][2];
    __shared__ __half sgT[4][64];

    const int jc  = blockIdx.x;
    const int bt  = blockIdx.y;
    const int o   = blockIdx.z;
    const int tid = threadIdx.x;
    const int b   = bt * 128 + tid;

    {
        int id  = ((o * 4 + bt) * 8 + jc) * 128 + tid;
        int row = id >> 9, c4 = id & 511;
        ((float4*)&out[row * OUTW])[c4] = ((const float4*)&x[row * CIN])[c4];
    }

    // own row: combine partials
    __half2 v[8];
    {
        const uint4* p0 = (const uint4*)&mh[b * MCOLS + o * KDIM];
        const uint4* p1 = (const uint4*)&mh[MSIZE + b * MCOLS + o * KDIM];
        __half2 a[8], c2[8];
        *(uint4*)&a[0]  = p0[0]; *(uint4*)&a[4]  = p0[1];
        *(uint4*)&c2[0] = p1[0]; *(uint4*)&c2[4] = p1[1];
#pragma unroll
        for (int i = 0; i < 8; ++i) v[i] = __hadd2(a[i], c2[i]);
    }
    __half2 vgb[4];
    {
        __half2 t01 = __hadd2(v[0], v[1]);
        __half2 t23 = __hadd2(v[2], v[3]);
        __half2 t45 = __hadd2(v[4], v[5]);
        __half2 t67 = __hadd2(v[6], v[7]);
        vgb[0] = __half2half2(__hadd(__low2half(t01), __high2half(t01)));
        vgb[1] = __half2half2(__hadd(__low2half(t23), __high2half(t23)));
        vgb[2] = __half2half2(__hadd(__low2half(t45), __high2half(t45)));
        vgb[3] = __half2half2(__hadd(__low2half(t67), __high2half(t67)));
    }

    if (tid < 64) {
        int j = jc * 64 + tid;
        const uint4* p0 = (const uint4*)&mh[j * MCOLS + o * KDIM];
        const uint4* p1 = (const uint4*)&mh[MSIZE + j * MCOLS + o * KDIM];
        __half2 a[8], c2[8], s[8];
        *(uint4*)&a[0]  = p0[0]; *(uint4*)&a[4]  = p0[1];
        *(uint4*)&c2[0] = p1[0]; *(uint4*)&c2[4] = p1[1];
#pragma unroll
        for (int i = 0; i < 8; ++i) s[i] = __hadd2(a[i], c2[i]);
        sjt[tid][0] = *(uint4*)&s[0];
        sjt[tid][1] = *(uint4*)&s[4];
        __half2 a01 = __hadd2(s[0], s[1]);
        __half2 a23 = __hadd2(s[2], s[3]);
        __half2 a45 = __hadd2(s[4], s[5]);
        __half2 a67 = __hadd2(s[6], s[7]);
        sgT[0][tid] = __hadd(__low2half(a01), __high2half(a01));
        sgT[1][tid] = __hadd(__low2half(a23), __high2half(a23));
        sgT[2][tid] = __hadd(__low2half(a45), __high2half(a45));
        sgT[3][tid] = __hadd(__low2half(a67), __high2half(a67));
    }
    __syncthreads();

    float acc = 0.0f;
#pragma unroll 4
    for (int jp2 = 0; jp2 < 32; ++jp2) {
        __half2 e0 = __habs2(__hsub2(vgb[0], *(const __half2*)&sgT[0][jp2 * 2]));
        __half2 e1 = __habs2(__hsub2(vgb[1], *(const __half2*)&sgT[1][jp2 * 2]));
        __half2 e2 = __habs2(__hsub2(vgb[2], *(const __half2*)&sgT[2][jp2 * 2]));
        __half2 e3 = __habs2(__hsub2(vgb[3], *(const __half2*)&sgT[3][jp2 * 2]));
        __half2 et = __hadd2(__hadd2(e0, e1), __hadd2(e2, e3));
        float mn = __half2float(__hmin(__low2half(et), __high2half(et)));
        if (__any_sync(0xffffffffu, mn < 30.0f)) {
#pragma unroll
            for (int t = 0; t < 2; ++t) {
                const int jj = jp2 * 2 + t;
                __half2 s[8];
                *(uint4*)&s[0] = sjt[jj][0];
                *(uint4*)&s[4] = sjt[jj][1];
                __half2 q0 = __habs2(__hsub2(v[0], s[0]));
                __half2 q1 = __habs2(__hsub2(v[1], s[1]));
                __half2 q2 = __habs2(__hsub2(v[2], s[2]));
                __half2 q3 = __habs2(__hsub2(v[3], s[3]));
                __half2 q4 = __habs2(__hsub2(v[4], s[4]));
                __half2 q5 = __habs2(__hsub2(v[5], s[5]));
                __half2 q6 = __habs2(__hsub2(v[6], s[6]));
                __half2 q7 = __habs2(__hsub2(v[7], s[7]));
                __half2 sm = __hadd2(__hadd2(__hadd2(q0, q1), __hadd2(q2, q3)),
                                     __hadd2(__hadd2(q4, q5), __hadd2(q6, q7)));
                float dist = __low2float(sm) + __high2float(sm);
                acc += __expf(-dist);
            }
        }
    }

    atomicAdd(&out[b * OUTW + CIN + o], acc);
}

extern "C" void kernel_launch(void* const* d_in, const int* in_sizes, int n_in,
                              void* d_out, int out_size)
{
    const float* x = (const float*)d_in[0];
    const float* T = (const float*)d_in[1];
    float* out = (float*)d_out;

    __half* mh;
    cudaGetSymbolAddress((void**)&mh, g_mh);

    prep_kernel<<<1552, 256>>>(x, T, out);
    gemm_bf16<<<dim3(MCOLS / 64, BATCH / 32, 2), 128>>>(mh);
    pairwise_kernel<<<dim3(8, 4, OFEAT), 128>>>(mh, x, out);
}

// round 13
// speedup vs baseline: 1.2004x; 1.0380x over previous
#include <cuda_runtime.h>
#include <cuda_fp16.h>
#include <cuda_fp8.h>

#define BATCH   512
#define CIN     2048
#define OFEAT   64
#define KDIM    16
#define MCOLS   1024
#define OUTW    2112

// Scratch (device globals; no allocs)
__device__ unsigned char g_xf8[BATCH * CIN];    // x  e4m3 [b][k], 1 MB
__device__ unsigned char g_Tf8[MCOLS * CIN];    // T^T e4m3 [n][k], 2 MB
__device__ __half        g_mh[BATCH * MCOLS];   // m fp16, 1 MB

// ---------------------------------------------------------------------------
// Prep: blocks [0,512): x -> e4m3 (8 floats/thread); [512,1024): T transpose
// + convert to e4m3 [n][k] via 64x64 shared tiles; [1024,1040): zero tail.
// ---------------------------------------------------------------------------
__global__ __launch_bounds__(256) void prep_kernel(
    const float* __restrict__ x, const float* __restrict__ T, float* __restrict__ out)
{
    const int bid = blockIdx.x;
    const int tid = threadIdx.x;
    if (bid < 512) {                             // x: 131072 x (8 floats -> 8 bytes)
        int id = bid * 256 + tid;
        float4 v0 = ((const float4*)x)[id * 2];
        float4 v1 = ((const float4*)x)[id * 2 + 1];
        unsigned a = (unsigned)__nv_cvt_float2_to_fp8x2(make_float2(v0.x, v0.y), __NV_SATFINITE, __NV_E4M3)
                   | ((unsigned)__nv_cvt_float2_to_fp8x2(make_float2(v0.z, v0.w), __NV_SATFINITE, __NV_E4M3) << 16);
        unsigned b = (unsigned)__nv_cvt_float2_to_fp8x2(make_float2(v1.x, v1.y), __NV_SATFINITE, __NV_E4M3)
                   | ((unsigned)__nv_cvt_float2_to_fp8x2(make_float2(v1.z, v1.w), __NV_SATFINITE, __NV_E4M3) << 16);
        *(uint2*)&g_xf8[id * 8] = make_uint2(a, b);
    } else if (bid < 1024) {                     // T transpose: 512 tiles 64x64
        __shared__ unsigned char st[64][96];     // [n][k] bytes, 96 = 16B-mult
        int t  = bid - 512;
        int k0 = (t >> 4) * 64;                  // 32 k-tiles
        int n0 = (t & 15) * 64;                  // 16 n-tiles
        int kk = tid >> 4, n4 = (tid & 15) * 4;
#pragma unroll
        for (int r = 0; r < 4; ++r) {
            int k = kk + r * 16;
            float4 v = *(const float4*)&T[(k0 + k) * MCOLS + n0 + n4];
            st[n4 + 0][k] = __nv_cvt_float_to_fp8(v.x, __NV_SATFINITE, __NV_E4M3);
            st[n4 + 1][k] = __nv_cvt_float_to_fp8(v.y, __NV_SATFINITE, __NV_E4M3);
            st[n4 + 2][k] = __nv_cvt_float_to_fp8(v.z, __NV_SATFINITE, __NV_E4M3);
            st[n4 + 3][k] = __nv_cvt_float_to_fp8(v.w, __NV_SATFINITE, __NV_E4M3);
        }
        __syncthreads();
        int n = tid >> 2, ks = (tid & 3) * 16;
        uint4 u = *(uint4*)&st[n][ks];
        *(uint4*)&g_Tf8[(n0 + n) * CIN + k0 + ks] = u;
    } else {                                     // zero tail: 8192 float4
        int base = (bid - 1024) * 512 + tid;
#pragma unroll
        for (int it = 0; it < 2; ++it) {
            int i = base + it * 256;
            int row = i >> 4, c = i & 15;
            ((float4*)&out[row * OUTW + CIN])[c] = make_float4(0.f, 0.f, 0.f, 0.f);
        }
    }
}

// ---------------------------------------------------------------------------
// GEMM e4m3: m = x @ T, mma.m16n8k32, 4-stage cp.async ring.
// BM=32 BN=64 BK=64(bytes), 128 threads (4 warps, 2m x 2n, warp tile 16x32).
// grid 16x16 = 256 blocks, 32 panels. A [m][k], B [n][k]; non-trans ldmatrix.
// ---------------------------------------------------------------------------
__device__ __forceinline__ void cp16(unsigned s, const void* g) {
    asm volatile("cp.async.cg.shared.global [%0], [%1], 16;" :: "r"(s), "l"(g));
}
#define CP_COMMIT()  asm volatile("cp.async.commit_group;")
#define CP_WAIT(N)   asm volatile("cp.async.wait_group %0;" :: "n"(N))

__device__ __forceinline__ void ldm_x4(unsigned* r, unsigned addr) {
    asm volatile("ldmatrix.sync.aligned.m8n8.x4.shared.b16 {%0,%1,%2,%3}, [%4];"
        : "=r"(r[0]), "=r"(r[1]), "=r"(r[2]), "=r"(r[3]) : "r"(addr));
}
__device__ __forceinline__ void mma_fp8(float* d, const unsigned* a, const unsigned* b) {
    asm volatile(
        "mma.sync.aligned.m16n8k32.row.col.f32.e4m3.e4m3.f32 "
        "{%0,%1,%2,%3}, {%4,%5,%6,%7}, {%8,%9}, {%0,%1,%2,%3};\n"
        : "+f"(d[0]), "+f"(d[1]), "+f"(d[2]), "+f"(d[3])
        : "r"(a[0]), "r"(a[1]), "r"(a[2]), "r"(a[3]), "r"(b[0]), "r"(b[1]));
}

#define NSTAGE 4
#define NPANEL 32   // CIN / 64

__global__ __launch_bounds__(128) void gemm_fp8(__half* __restrict__ mh)
{
    __shared__ unsigned char As[NSTAGE][32][80];   // 64B rows + pad
    __shared__ unsigned char Bs[NSTAGE][64][80];

    const int tid  = threadIdx.x;
    const int lane = tid & 31;
    const int wid  = tid >> 5;
    const int wm   = wid & 1;      // 2 m-warps of 16
    const int wn   = wid >> 1;     // 2 n-warps of 32
    const int row0 = blockIdx.y * 32;
    const int col0 = blockIdx.x * 64;

    // staging: A 32x64B (128 segs, 1/thread), B 64x64B (256 segs, 2/thread)
    const int aRow = tid >> 2, aC = (tid & 3) * 16;
    const int bRow = tid >> 1, bC = (tid & 1) * 32;

    const unsigned char* gA = &g_xf8[(row0 + aRow) * CIN + aC];
    const unsigned char* gB = &g_Tf8[(col0 + bRow) * CIN + bC];

    float d[2][2][4];
#pragma unroll
    for (int i = 0; i < 2; ++i)
#pragma unroll
        for (int j = 0; j < 2; ++j)
#pragma unroll
            for (int k = 0; k < 4; ++k) d[i][j][k] = 0.0f;

    // prologue: stages 0..2
#pragma unroll
    for (int s = 0; s < NSTAGE - 1; ++s) {
        cp16(__cvta_generic_to_shared(&As[s][aRow][aC]), gA + s * 64);
        cp16(__cvta_generic_to_shared(&Bs[s][bRow][bC]),      gB + s * 64);
        cp16(__cvta_generic_to_shared(&Bs[s][bRow][bC + 16]), gB + s * 64 + 16);
        CP_COMMIT();
    }

    for (int p = 0; p < NPANEL; ++p) {
        CP_WAIT(NSTAGE - 2);     // my stage-p copies complete
        __syncthreads();         // all copies visible; all threads done with p-1
        if (p + NSTAGE - 1 < NPANEL) {
            const int s  = (p + NSTAGE - 1) & (NSTAGE - 1);
            const int k0 = (p + NSTAGE - 1) * 64;
            cp16(__cvta_generic_to_shared(&As[s][aRow][aC]), gA + k0);
            cp16(__cvta_generic_to_shared(&Bs[s][bRow][bC]),      gB + k0);
            cp16(__cvta_generic_to_shared(&Bs[s][bRow][bC + 16]), gB + k0 + 16);
        }
        CP_COMMIT();
        const int buf = p & (NSTAGE - 1);

#pragma unroll
        for (int kk = 0; kk < 64; kk += 32) {
            // A frag (k32): m0 rows0-7 k0-15 | m1 rows8-15 k0-15 | m2/m3 +16B
            unsigned a[4];
            unsigned adrA = __cvta_generic_to_shared(
                &As[buf][wm * 16 + (lane & 15)][kk + (lane >> 4) * 16]);
            ldm_x4(a, adrA);
#pragma unroll
            for (int bg = 0; bg < 2; ++bg) {
                // B frags: m0 n0-7 k0 | m1 n0-7 k16 | m2 n8-15 k0 | m3 n8-15 k16
                unsigned bb[4];
                unsigned adrB = __cvta_generic_to_shared(
                    &Bs[buf][wn * 32 + bg * 16 + (lane & 7) + ((lane >> 4) & 1) * 8]
                       [kk + ((lane >> 3) & 1) * 16]);
                ldm_x4(bb, adrB);
                mma_fp8(d[bg][0], a, bb);       // n octet 0: {m0,m1}
                mma_fp8(d[bg][1], a, bb + 2);   // n octet 1: {m2,m3}
            }
        }
    }

    // epilogue -> fp16
    const int g = lane >> 2, c = lane & 3;
#pragma unroll
    for (int bg = 0; bg < 2; ++bg)
#pragma unroll
        for (int h = 0; h < 2; ++h) {
            int row = row0 + wm * 16 + g;
            int col = col0 + wn * 32 + bg * 16 + h * 8 + c * 2;
            *(__half2*)&mh[row * MCOLS + col] =
                __floats2half2_rn(d[bg][h][0], d[bg][h][1]);
            *(__half2*)&mh[(row + 8) * MCOLS + col] =
                __floats2half2_rn(d[bg][h][2], d[bg][h][3]);
        }
}

// ---------------------------------------------------------------------------
// Pairwise: out[b, 2048+o] += sum_{j in chunk} exp(-L1(m[b,o,:], m[j,o,:]))
// grid (jc=8, bt=4, o=64) x 128 thr. Folds x -> out copy (one float4/thread).
// ---------------------------------------------------------------------------
__global__ __launch_bounds__(128) void pairwise_kernel(
    const __half* __restrict__ mh, const float* __restrict__ x, float* __restrict__ out)
{
    __shared__ uint4  sjt[64][2];
    __shared__ __half sgT[4][64];

    const int jc  = blockIdx.x;
    const int bt  = blockIdx.y;
    const int o   = blockIdx.z;
    const int tid = threadIdx.x;
    const int b   = bt * 128 + tid;

    {
        int id  = ((o * 4 + bt) * 8 + jc) * 128 + tid;
        int row = id >> 9, c4 = id & 511;
        ((float4*)&out[row * OUTW])[c4] = ((const float4*)&x[row * CIN])[c4];
    }

    const uint4* vp = (const uint4*)&mh[b * MCOLS + o * KDIM];
    uint4 u0 = vp[0], u1 = vp[1];
    __half2 v[8];
    *(uint4*)&v[0] = u0;
    *(uint4*)&v[4] = u1;
    __half2 vgb[4];
    {
        __half2 t01 = __hadd2(v[0], v[1]);
        __half2 t23 = __hadd2(v[2], v[3]);
        __half2 t45 = __hadd2(v[4], v[5]);
        __half2 t67 = __hadd2(v[6], v[7]);
        vgb[0] = __half2half2(__hadd(__low2half(t01), __high2half(t01)));
        vgb[1] = __half2half2(__hadd(__low2half(t23), __high2half(t23)));
        vgb[2] = __half2half2(__hadd(__low2half(t45), __high2half(t45)));
        vgb[3] = __half2half2(__hadd(__low2half(t67), __high2half(t67)));
    }

    if (tid < 64) {
        int j = jc * 64 + tid;
        const uint4* jp = (const uint4*)&mh[j * MCOLS + o * KDIM];
        uint4 w0 = jp[0], w1 = jp[1];
        sjt[tid][0] = w0;
        sjt[tid][1] = w1;
        __half2 s[8];
        *(uint4*)&s[0] = w0;
        *(uint4*)&s[4] = w1;
        __half2 a01 = __hadd2(s[0], s[1]);
        __half2 a23 = __hadd2(s[2], s[3]);
        __half2 a45 = __hadd2(s[4], s[5]);
        __half2 a67 = __hadd2(s[6], s[7]);
        sgT[0][tid] = __hadd(__low2half(a01), __high2half(a01));
        sgT[1][tid] = __hadd(__low2half(a23), __high2half(a23));
        sgT[2][tid] = __hadd(__low2half(a45), __high2half(a45));
        sgT[3][tid] = __hadd(__low2half(a67), __high2half(a67));
    }
    __syncthreads();

    float acc = 0.0f;
#pragma unroll 4
    for (int jp2 = 0; jp2 < 32; ++jp2) {
        __half2 e0 = __habs2(__hsub2(vgb[0], *(const __half2*)&sgT[0][jp2 * 2]));
        __half2 e1 = __habs2(__hsub2(vgb[1], *(const __half2*)&sgT[1][jp2 * 2]));
        __half2 e2 = __habs2(__hsub2(vgb[2], *(const __half2*)&sgT[2][jp2 * 2]));
        __half2 e3 = __habs2(__hsub2(vgb[3], *(const __half2*)&sgT[3][jp2 * 2]));
        __half2 et = __hadd2(__hadd2(e0, e1), __hadd2(e2, e3));
        float mn = __half2float(__hmin(__low2half(et), __high2half(et)));
        if (__any_sync(0xffffffffu, mn < 30.0f)) {
#pragma unroll
            for (int t = 0; t < 2; ++t) {
                const int jj = jp2 * 2 + t;
                __half2 s[8];
                *(uint4*)&s[0] = sjt[jj][0];
                *(uint4*)&s[4] = sjt[jj][1];
                __half2 q0 = __habs2(__hsub2(v[0], s[0]));
                __half2 q1 = __habs2(__hsub2(v[1], s[1]));
                __half2 q2 = __habs2(__hsub2(v[2], s[2]));
                __half2 q3 = __habs2(__hsub2(v[3], s[3]));
                __half2 q4 = __habs2(__hsub2(v[4], s[4]));
                __half2 q5 = __habs2(__hsub2(v[5], s[5]));
                __half2 q6 = __habs2(__hsub2(v[6], s[6]));
                __half2 q7 = __habs2(__hsub2(v[7], s[7]));
                __half2 sm = __hadd2(__hadd2(__hadd2(q0, q1), __hadd2(q2, q3)),
                                     __hadd2(__hadd2(q4, q5), __hadd2(q6, q7)));
                float dist = __low2float(sm) + __high2float(sm);
                acc += __expf(-dist);
            }
        }
    }

    atomicAdd(&out[b * OUTW + CIN + o], acc);
}

extern "C" void kernel_launch(void* const* d_in, const int* in_sizes, int n_in,
                              void* d_out, int out_size)
{
    const float* x = (const float*)d_in[0];
    const float* T = (const float*)d_in[1];
    float* out = (float*)d_out;

    __half* mh;
    cudaGetSymbolAddress((void**)&mh, g_mh);

    prep_kernel<<<1040, 256>>>(x, T, out);
    gemm_fp8<<<dim3(MCOLS / 64, BATCH / 32), 128>>>(mh);
    pairwise_kernel<<<dim3(8, 4, OFEAT), 128>>>(mh, x, out);
}